// round 6
// baseline (speedup 1.0000x reference)
#include <cuda_runtime.h>
#include <cuda_bf16.h>

#define BB   16
#define CC   192
#define TXN  1024
#define MAXY 4096

// Scratch: token index per output frame (-1 = no token -> z = noise)
__device__ int g_idx[BB * MAXY];

// One block per batch, 1024 threads.
__global__ void build_map_kernel(const float* __restrict__ logw,
                                 const int* __restrict__ x_lengths,
                                 float* __restrict__ y_mask_out) {
    __shared__ int warp_sums[32];
    const int b    = blockIdx.x;
    const int t    = threadIdx.x;
    const int lane = t & 31;
    const int wid  = t >> 5;

    const int xlen = max(x_lengths[b], 1);
    int w = 0;
    if (t < xlen) {
        // accurate expf: feeds ceil(), ulp flips at integer boundaries matter
        w = (int)ceilf(expf(logw[b * TXN + t]));
    }

    // warp-level inclusive scan
    int c = w;
    #pragma unroll
    for (int o = 1; o < 32; o <<= 1) {
        int v = __shfl_up_sync(0xffffffffu, c, o);
        if (lane >= o) c += v;
    }
    if (lane == 31) warp_sums[wid] = c;
    __syncthreads();
    if (wid == 0) {
        int v = warp_sums[lane];
        #pragma unroll
        for (int o = 1; o < 32; o <<= 1) {
            int u = __shfl_up_sync(0xffffffffu, v, o);
            if (lane >= o) v += u;
        }
        warp_sums[lane] = v;
    }
    __syncthreads();

    const int base  = (wid > 0) ? warp_sums[wid - 1] : 0;
    const int cum   = base + c;               // inclusive prefix sum
    const int total = warp_sums[31];
    const int ylen  = min(max(total, 1), MAXY);

    int* __restrict__ row = g_idx + b * MAXY;

    // band scatter: frames [cum-w, cum) belong to token t
    const int end = min(cum, MAXY);
    for (int ty = cum - w; ty < end; ty++) row[ty] = t;

    // tail fill: frames beyond total have no token
    const int tail0 = min(total, MAXY);
    for (int ty = tail0 + t; ty < MAXY; ty += TXN) row[ty] = -1;

    // y_mask, one float4 per thread
    if (y_mask_out != nullptr) {
        const int v0 = t * 4;
        float4 m;
        m.x = (v0 + 0 < ylen) ? 1.0f : 0.0f;
        m.y = (v0 + 1 < ylen) ? 1.0f : 0.0f;
        m.z = (v0 + 2 < ylen) ? 1.0f : 0.0f;
        m.w = (v0 + 3 < ylen) ? 1.0f : 0.0f;
        reinterpret_cast<float4*>(y_mask_out + b * MAXY)[t] = m;
    }
}

// One block per (b,c) row, 256 threads x 4 float4 = 4096 ty.
// R3's winning schedule: ALL global loads (m row, s row, 4x noise, 4x idx)
// issue before the single barrier, so no block-start LDG bubble. logs are
// pre-exponentiated during staging -> post-barrier chain is LDS->FFMA->STG.
__global__ void __launch_bounds__(256)
expand_kernel(const float* __restrict__ m_p,
              const float* __restrict__ logs_p,
              const float* __restrict__ noise,
              float* __restrict__ z) {
    __shared__ float sm[TXN];
    __shared__ float se[TXN];

    const int bc  = blockIdx.x;      // 0..BB*CC-1
    const int b   = bc / CC;
    const int tid = threadIdx.x;

    const float4* __restrict__ nz4 = reinterpret_cast<const float4*>(noise) + (size_t)bc * (MAXY / 4);
    float4*       __restrict__ z4  = reinterpret_cast<float4*>(z)           + (size_t)bc * (MAXY / 4);
    const int4*   __restrict__ ix4 = reinterpret_cast<const int4*>(g_idx)   + b * (MAXY / 4);

    // ---- issue ALL global loads before the barrier ----
    float4 mv = __ldcs(&reinterpret_cast<const float4*>(m_p    + (size_t)bc * TXN)[tid]);
    float4 sv = __ldcs(&reinterpret_cast<const float4*>(logs_p + (size_t)bc * TXN)[tid]);

    float4 n[4];
    int4   ix[4];
    #pragma unroll
    for (int j = 0; j < 4; j++) n[j] = __ldcs(&nz4[tid + j * 256]);
    #pragma unroll
    for (int j = 0; j < 4; j++) ix[j] = ix4[tid + j * 256];

    // stage: m as-is, logs pre-exponentiated (MUFU hoisted off the hot chain)
    reinterpret_cast<float4*>(sm)[tid] = mv;
    {
        float4 e;
        e.x = __expf(sv.x); e.y = __expf(sv.y);
        e.z = __expf(sv.z); e.w = __expf(sv.w);
        reinterpret_cast<float4*>(se)[tid] = e;
    }
    __syncthreads();

    // ---- compute: LDS (broadcast-friendly) + FFMA + streamed store ----
    #pragma unroll
    for (int j = 0; j < 4; j++) {
        float4 o;
        o.x = (ix[j].x >= 0) ? fmaf(n[j].x, se[ix[j].x], sm[ix[j].x]) : n[j].x;
        o.y = (ix[j].y >= 0) ? fmaf(n[j].y, se[ix[j].y], sm[ix[j].y]) : n[j].y;
        o.z = (ix[j].z >= 0) ? fmaf(n[j].z, se[ix[j].z], sm[ix[j].z]) : n[j].z;
        o.w = (ix[j].w >= 0) ? fmaf(n[j].w, se[ix[j].w], sm[ix[j].w]) : n[j].w;
        __stcs(&z4[tid + j * 256], o);
    }
}

extern "C" void kernel_launch(void* const* d_in, const int* in_sizes, int n_in,
                              void* d_out, int out_size) {
    const float* m_p    = (const float*)d_in[0];
    const float* logs_p = (const float*)d_in[1];
    const float* logw   = (const float*)d_in[2];
    const float* noise  = (const float*)d_in[3];
    const int*   xlens  = (const int*)d_in[4];

    float* out = (float*)d_out;
    const int zsize = BB * CC * MAXY;            // 12,582,912
    float* z = out;
    float* y_mask = (out_size >= zsize + BB * MAXY) ? (out + zsize) : nullptr;

    build_map_kernel<<<BB, TXN>>>(logw, xlens, y_mask);
    expand_kernel<<<BB * CC, 256>>>(m_p, logs_p, noise, z);
}

// round 7
// speedup vs baseline: 1.1115x; 1.1115x over previous
#include <cuda_runtime.h>
#include <cuda_bf16.h>

#define BB   16
#define CC   192
#define TXN  1024
#define MAXY 4096

// Scratch: token index per output frame (-1 = no token -> z = noise)
__device__ int g_idx[BB * MAXY];

// One block per batch, 1024 threads. Triggers PDL at entry so the expand
// kernel's independent prologue overlaps with this kernel.
__global__ void build_map_kernel(const float* __restrict__ logw,
                                 const int* __restrict__ x_lengths,
                                 float* __restrict__ y_mask_out) {
#if __CUDA_ARCH__ >= 900
    cudaTriggerProgrammaticLaunchCompletion();
#endif
    __shared__ int warp_sums[32];
    const int b    = blockIdx.x;
    const int t    = threadIdx.x;
    const int lane = t & 31;
    const int wid  = t >> 5;

    const int xlen = max(x_lengths[b], 1);
    int w = 0;
    if (t < xlen) {
        // accurate expf: feeds ceil(), ulp flips at integer boundaries matter
        w = (int)ceilf(expf(logw[b * TXN + t]));
    }

    // warp-level inclusive scan
    int c = w;
    #pragma unroll
    for (int o = 1; o < 32; o <<= 1) {
        int v = __shfl_up_sync(0xffffffffu, c, o);
        if (lane >= o) c += v;
    }
    if (lane == 31) warp_sums[wid] = c;
    __syncthreads();
    if (wid == 0) {
        int v = warp_sums[lane];
        #pragma unroll
        for (int o = 1; o < 32; o <<= 1) {
            int u = __shfl_up_sync(0xffffffffu, v, o);
            if (lane >= o) v += u;
        }
        warp_sums[lane] = v;
    }
    __syncthreads();

    const int base  = (wid > 0) ? warp_sums[wid - 1] : 0;
    const int cum   = base + c;               // inclusive prefix sum
    const int total = warp_sums[31];
    const int ylen  = min(max(total, 1), MAXY);

    int* __restrict__ row = g_idx + b * MAXY;

    // band scatter: frames [cum-w, cum) belong to token t
    const int end = min(cum, MAXY);
    for (int ty = cum - w; ty < end; ty++) row[ty] = t;

    // tail fill: frames beyond total have no token
    const int tail0 = min(total, MAXY);
    for (int ty = tail0 + t; ty < MAXY; ty += TXN) row[ty] = -1;

    // y_mask, one float4 per thread
    if (y_mask_out != nullptr) {
        const int v0 = t * 4;
        float4 m;
        m.x = (v0 + 0 < ylen) ? 1.0f : 0.0f;
        m.y = (v0 + 1 < ylen) ? 1.0f : 0.0f;
        m.z = (v0 + 2 < ylen) ? 1.0f : 0.0f;
        m.w = (v0 + 3 < ylen) ? 1.0f : 0.0f;
        reinterpret_cast<float4*>(y_mask_out + b * MAXY)[t] = m;
    }
}

// One block per (b,c) row, 512 threads x 2 float4 = 4096 ty.
// Prologue (m/s staging + exp + noise loads) runs BEFORE the PDL grid sync,
// overlapping build_map. Only the g_idx loads wait for it.
// Staging split: warps 0-7 load m row, warps 8-15 load + exp the s row.
__global__ void __launch_bounds__(512)
expand_kernel(const float* __restrict__ m_p,
              const float* __restrict__ logs_p,
              const float* __restrict__ noise,
              float* __restrict__ z) {
    __shared__ float sm[TXN];
    __shared__ float se[TXN];

    const int bc  = blockIdx.x;      // 0..BB*CC-1
    const int b   = bc / CC;
    const int tid = threadIdx.x;

    const float4* __restrict__ nz4 = reinterpret_cast<const float4*>(noise) + (size_t)bc * (MAXY / 4);
    float4*       __restrict__ z4  = reinterpret_cast<float4*>(z)           + (size_t)bc * (MAXY / 4);
    const int4*   __restrict__ ix4 = reinterpret_cast<const int4*>(g_idx)   + b * (MAXY / 4);

    // ---- independent prologue (no g_idx): split row staging + noise loads ----
    if (tid < 256) {
        float4 mv = reinterpret_cast<const float4*>(m_p + (size_t)bc * TXN)[tid];
        reinterpret_cast<float4*>(sm)[tid] = mv;
    } else {
        const int u = tid - 256;
        float4 sv = reinterpret_cast<const float4*>(logs_p + (size_t)bc * TXN)[u];
        float4 e;
        e.x = __expf(sv.x); e.y = __expf(sv.y);
        e.z = __expf(sv.z); e.w = __expf(sv.w);
        reinterpret_cast<float4*>(se)[u] = e;
    }

    float4 n[2];
    #pragma unroll
    for (int j = 0; j < 2; j++) n[j] = __ldcs(&nz4[tid + j * 512]);

    __syncthreads();

    // ---- wait for build_map's g_idx, then finish ----
#if __CUDA_ARCH__ >= 900
    cudaGridDependencySynchronize();
#endif

    int4 ix[2];
    #pragma unroll
    for (int j = 0; j < 2; j++) ix[j] = ix4[tid + j * 512];

    #pragma unroll
    for (int j = 0; j < 2; j++) {
        float4 o;
        o.x = (ix[j].x >= 0) ? fmaf(n[j].x, se[ix[j].x], sm[ix[j].x]) : n[j].x;
        o.y = (ix[j].y >= 0) ? fmaf(n[j].y, se[ix[j].y], sm[ix[j].y]) : n[j].y;
        o.z = (ix[j].z >= 0) ? fmaf(n[j].z, se[ix[j].z], sm[ix[j].z]) : n[j].z;
        o.w = (ix[j].w >= 0) ? fmaf(n[j].w, se[ix[j].w], sm[ix[j].w]) : n[j].w;
        __stcs(&z4[tid + j * 512], o);
    }
}

extern "C" void kernel_launch(void* const* d_in, const int* in_sizes, int n_in,
                              void* d_out, int out_size) {
    const float* m_p    = (const float*)d_in[0];
    const float* logs_p = (const float*)d_in[1];
    const float* logw   = (const float*)d_in[2];
    const float* noise  = (const float*)d_in[3];
    const int*   xlens  = (const int*)d_in[4];

    float* out = (float*)d_out;
    const int zsize = BB * CC * MAXY;            // 12,582,912
    float* z = out;
    float* y_mask = (out_size >= zsize + BB * MAXY) ? (out + zsize) : nullptr;

    build_map_kernel<<<BB, TXN>>>(logw, xlens, y_mask);

    // expand with programmatic dependent launch: its prologue overlaps
    // build_map; cudaGridDependencySynchronize() guards the g_idx reads.
    cudaLaunchConfig_t cfg = {};
    cfg.gridDim  = dim3(BB * CC);
    cfg.blockDim = dim3(512);
    cfg.dynamicSmemBytes = 0;
    cfg.stream = 0;
    cudaLaunchAttribute attr[1];
    attr[0].id = cudaLaunchAttributeProgrammaticStreamSerialization;
    attr[0].val.programmaticStreamSerializationAllowed = 1;
    cfg.attrs = attr;
    cfg.numAttrs = 1;
    cudaLaunchKernelEx(&cfg, expand_kernel, m_p, logs_p, noise, z);
}

// round 8
// speedup vs baseline: 1.2318x; 1.1083x over previous
#include <cuda_runtime.h>
#include <cuda_bf16.h>

#define BB   16
#define CC   192
#define TXN  1024
#define MAXY 4096

// Scratch: token index per output frame (-1 = no token -> z = noise)
__device__ int g_idx[BB * MAXY];

// One block per batch, 1024 threads.
// PDL trigger fires AFTER g_idx is fully written (y_mask, which expand never
// reads, is written after the trigger).
__global__ void build_map_kernel(const float* __restrict__ logw,
                                 const int* __restrict__ x_lengths,
                                 float* __restrict__ y_mask_out) {
    __shared__ int warp_sums[32];
    const int b    = blockIdx.x;
    const int t    = threadIdx.x;
    const int lane = t & 31;
    const int wid  = t >> 5;

    const int xlen = max(x_lengths[b], 1);
    int w = 0;
    if (t < xlen) {
        // accurate expf: feeds ceil(), ulp flips at integer boundaries matter
        w = (int)ceilf(expf(logw[b * TXN + t]));
    }

    // warp-level inclusive scan
    int c = w;
    #pragma unroll
    for (int o = 1; o < 32; o <<= 1) {
        int v = __shfl_up_sync(0xffffffffu, c, o);
        if (lane >= o) c += v;
    }
    if (lane == 31) warp_sums[wid] = c;
    __syncthreads();
    if (wid == 0) {
        int v = warp_sums[lane];
        #pragma unroll
        for (int o = 1; o < 32; o <<= 1) {
            int u = __shfl_up_sync(0xffffffffu, v, o);
            if (lane >= o) v += u;
        }
        warp_sums[lane] = v;
    }
    __syncthreads();

    const int base  = (wid > 0) ? warp_sums[wid - 1] : 0;
    const int cum   = base + c;               // inclusive prefix sum
    const int total = warp_sums[31];
    const int ylen  = min(max(total, 1), MAXY);

    int* __restrict__ row = g_idx + b * MAXY;

    // band scatter: frames [cum-w, cum) belong to token t
    const int end = min(cum, MAXY);
    for (int ty = cum - w; ty < end; ty++) row[ty] = t;

    // tail fill: frames beyond total have no token
    const int tail0 = min(total, MAXY);
    for (int ty = tail0 + t; ty < MAXY; ty += TXN) row[ty] = -1;

    // g_idx complete for this block -> release to dependent kernel
    __syncthreads();
#if __CUDA_ARCH__ >= 900
    cudaTriggerProgrammaticLaunchCompletion();
#endif

    // y_mask, one float4 per thread (not read by expand)
    if (y_mask_out != nullptr) {
        const int v0 = t * 4;
        float4 m;
        m.x = (v0 + 0 < ylen) ? 1.0f : 0.0f;
        m.y = (v0 + 1 < ylen) ? 1.0f : 0.0f;
        m.z = (v0 + 2 < ylen) ? 1.0f : 0.0f;
        m.w = (v0 + 3 < ylen) ? 1.0f : 0.0f;
        reinterpret_cast<float4*>(y_mask_out + b * MAXY)[t] = m;
    }
}

// EXACT R3 structure (measured 17.8us): one block per (b,c) row, 256 threads,
// 4x float4, all global loads pre-barrier, __expf in compute chain.
// Only change: gridDependencySynchronize before the g_idx loads, so the
// m/s/noise loads overlap build_map via PDL.
__global__ void __launch_bounds__(256)
expand_kernel(const float* __restrict__ m_p,
              const float* __restrict__ logs_p,
              const float* __restrict__ noise,
              float* __restrict__ z) {
    __shared__ float sm[TXN];
    __shared__ float ss[TXN];

    const int bc  = blockIdx.x;      // 0..BB*CC-1
    const int b   = bc / CC;
    const int tid = threadIdx.x;

    const float4* __restrict__ nz4 = reinterpret_cast<const float4*>(noise) + (size_t)bc * (MAXY / 4);
    float4*       __restrict__ z4  = reinterpret_cast<float4*>(z)           + (size_t)bc * (MAXY / 4);
    const int4*   __restrict__ ix4 = reinterpret_cast<const int4*>(g_idx)   + b * (MAXY / 4);
    const float4* __restrict__ m4  = reinterpret_cast<const float4*>(m_p    + (size_t)bc * TXN);
    const float4* __restrict__ s4  = reinterpret_cast<const float4*>(logs_p + (size_t)bc * TXN);

    // ---- independent loads: overlap build_map under PDL ----
    float4 mv = m4[tid];
    float4 sv = s4[tid];

    float4 n[4];
    #pragma unroll
    for (int j = 0; j < 4; j++) n[j] = __ldcs(&nz4[tid + j * 256]);

    // ---- wait for g_idx, then the dependent loads ----
#if __CUDA_ARCH__ >= 900
    cudaGridDependencySynchronize();
#endif
    int4 ix[4];
    #pragma unroll
    for (int j = 0; j < 4; j++) ix[j] = ix4[tid + j * 256];

    reinterpret_cast<float4*>(sm)[tid] = mv;
    reinterpret_cast<float4*>(ss)[tid] = sv;
    __syncthreads();

    // ---- compute: LDS gathers (broadcast-friendly), MUFU exp, FMA ----
    #pragma unroll
    for (int j = 0; j < 4; j++) {
        const int   tt[4] = {ix[j].x, ix[j].y, ix[j].z, ix[j].w};
        const float nv[4] = {n[j].x, n[j].y, n[j].z, n[j].w};
        float ov[4];
        #pragma unroll
        for (int k = 0; k < 4; k++) {
            const int t = tt[k];
            ov[k] = (t >= 0) ? fmaf(nv[k], __expf(ss[t]), sm[t]) : nv[k];
        }
        __stcs(&z4[tid + j * 256], make_float4(ov[0], ov[1], ov[2], ov[3]));
    }
}

extern "C" void kernel_launch(void* const* d_in, const int* in_sizes, int n_in,
                              void* d_out, int out_size) {
    const float* m_p    = (const float*)d_in[0];
    const float* logs_p = (const float*)d_in[1];
    const float* logw   = (const float*)d_in[2];
    const float* noise  = (const float*)d_in[3];
    const int*   xlens  = (const int*)d_in[4];

    float* out = (float*)d_out;
    const int zsize = BB * CC * MAXY;            // 12,582,912
    float* z = out;
    float* y_mask = (out_size >= zsize + BB * MAXY) ? (out + zsize) : nullptr;

    build_map_kernel<<<BB, TXN>>>(logw, xlens, y_mask);

    // expand with programmatic dependent launch: independent loads overlap
    // build_map; cudaGridDependencySynchronize() guards the g_idx reads.
    cudaLaunchConfig_t cfg = {};
    cfg.gridDim  = dim3(BB * CC);
    cfg.blockDim = dim3(256);
    cfg.dynamicSmemBytes = 0;
    cfg.stream = 0;
    cudaLaunchAttribute attr[1];
    attr[0].id = cudaLaunchAttributeProgrammaticStreamSerialization;
    attr[0].val.programmaticStreamSerializationAllowed = 1;
    cfg.attrs = attr;
    cfg.numAttrs = 1;
    cudaLaunchKernelEx(&cfg, expand_kernel, m_p, logs_p, noise, z);
}